// round 6
// baseline (speedup 1.0000x reference)
#include <cuda_runtime.h>

// ---------------------------------------------------------------------------
// EventGRUBayes — block-cooperative solver: 128 blocks x 128 threads,
// all 8 samples of a block share every weight-row stream (S=8 reuse).
// Thread t owns 2 of the 256 pass1 rows (ghr/ghz for t<64, two W1 rows for
// t>=64) and accumulates them against all 8 h vectors (broadcast LDS).
// Pass2 (ghh) on t<64 runs concurrently with the output head on t>=64.
// Events: fired samples split alternately between thread halves; last
// duplicate obs wins (precomputed winner table). Packed fma.rn.f32x2 math.
// ---------------------------------------------------------------------------

#define B_     1024
#define NEV    400
#define NSTEPS 500
#define OPE_   256
#define TOT_   (NEV * OPE_)
#define DT_    0.01f

typedef unsigned long long ull;

// shared-memory float offsets (weight rows padded 64->68 / 8->12)
#define OF_GHR 0
#define OF_GHZ 4352
#define OF_GHH 8704
#define OF_WHH 13056
#define OF_W1  26112
#define OF_WIH 34816
#define OF_BIH 37120
#define OF_BHH 37312
#define OF_GXB 37504
#define OF_OB1 37696
#define OF_W2  37824
#define OF_OB2 38080
#define OF_HS  38084          // [8][64] h
#define OF_RS  38596          // [8][64] r*h   (OF_HS + 512 -> hp[s][i+128])
#define OF_DD  39108          // [8][132] head hidden (padded stride)
#define OF_WIN 40164          // 2x8 ints
#define OF_XV  40180          // [2][8][8] prefetched X rows
#define SMEM_FLOATS 40308     // 161232 bytes

__device__ int g_winner[NEV * B_];   // winner[step][sample] = max obs idx, -1

__global__ void winner_init_k() {
    int i = blockIdx.x * blockDim.x + threadIdx.x;
    if (i < NEV * B_) g_winner[i] = -1;
}
__global__ void winner_scatter_k(const int* __restrict__ sid) {
    int j = blockIdx.x * blockDim.x + threadIdx.x;
    if (j < TOT_) atomicMax(&g_winner[(j >> 8) * B_ + sid[j]], j);
}

__device__ __forceinline__ float sigm(float x) {
    return __fdividef(1.f, 1.f + __expf(-x));
}
__device__ __forceinline__ float tanh_f(float x) {
    float xc = fminf(fmaxf(x, -15.f), 15.f);
    float e  = __expf(-2.f * xc);
    return __fdividef(1.f - e, 1.f + e);
}

#define FMA2(d, a, b, c) \
    asm("fma.rn.f32x2 %0, %1, %2, %3;" : "=l"(d) : "l"(a), "l"(b), "l"(c))

__device__ __forceinline__ float hadd2(ull v) {
    unsigned lo, hi;
    asm("mov.b64 {%0, %1}, %2;" : "=r"(lo), "=r"(hi) : "l"(v));
    return __uint_as_float(lo) + __uint_as_float(hi);
}
__device__ __forceinline__ float dot8(const float* __restrict__ w, float4 xa, float4 xb) {
    float4 A  = *reinterpret_cast<const float4*>(w);
    float4 Bv = *reinterpret_cast<const float4*>(w + 4);
    float s = A.x * xa.x;
    s = fmaf(A.y,  xa.y, s); s = fmaf(A.z,  xa.z, s); s = fmaf(A.w,  xa.w, s);
    s = fmaf(Bv.x, xb.x, s); s = fmaf(Bv.y, xb.y, s);
    s = fmaf(Bv.z, xb.z, s); s = fmaf(Bv.w, xb.w, s);
    return s;
}

__global__ __launch_bounds__(128, 1)
void ev_gru_main(
    const float* __restrict__ X,
    const float* __restrict__ covs,
    const float* __restrict__ cW1, const float* __restrict__ cb1,
    const float* __restrict__ cW2, const float* __restrict__ cb2,
    const float* __restrict__ gWih, const float* __restrict__ gWhh,
    const float* __restrict__ gbih, const float* __restrict__ gbhh,
    const float* __restrict__ gxb,
    const float* __restrict__ ghrW, const float* __restrict__ ghzW,
    const float* __restrict__ ghhW,
    const float* __restrict__ oW1,  const float* __restrict__ ob1,
    const float* __restrict__ oW2,  const float* __restrict__ ob2,
    float* __restrict__ out)
{
    extern __shared__ float sm[];
    const int tid = threadIdx.x;
    const int blk = blockIdx.x;
    const int j   = tid & 63;
    const int grp = tid >> 6;
    int* swin = (int*)(sm + OF_WIN);

    // t=0 winner prefetch (issue early, complete during staging)
    int pw0 = -1;
    if (tid >= 96 && tid < 104)
        pw0 = __ldg(g_winner + blk * 8 + (tid - 96));

    // ---- cooperative weight staging ----
    for (int i = tid; i < 64*64; i += 128) {
        int r = i >> 6, c = i & 63;
        sm[OF_GHR + r*68 + c] = ghrW[i];
        sm[OF_GHZ + r*68 + c] = ghzW[i];
        sm[OF_GHH + r*68 + c] = ghhW[i];
    }
    for (int i = tid; i < 192*64; i += 128) {
        int r = i >> 6, c = i & 63;
        sm[OF_WHH + r*68 + c] = gWhh[i];
    }
    for (int i = tid; i < 128*64; i += 128) {
        int r = i >> 6, c = i & 63;
        sm[OF_W1 + r*68 + c] = oW1[i];
    }
    for (int i = tid; i < 192*8; i += 128) {
        int r = i >> 3, c = i & 7;
        sm[OF_WIH + r*12 + c] = gWih[i];
    }
    for (int i = tid; i < 192; i += 128) {
        sm[OF_BIH + i] = gbih[i];
        sm[OF_BHH + i] = gbhh[i];
        sm[OF_GXB + i] = gxb[i];
    }
    sm[OF_OB1 + tid] = ob1[tid];
    for (int i = tid; i < 256; i += 128) sm[OF_W2 + i] = oW2[i];
    if (tid < 2) sm[OF_OB2 + tid] = ob2[tid];

    // ---- h0 init: 4 warps x 2 samples ----
    {
        const int warp = tid >> 5, lane = tid & 31, o2 = lane + 32;
        #pragma unroll
        for (int pick = 0; pick < 2; pick++) {
            const int s = warp * 2 + pick;
            const int b = blk * 8 + s;
            float* hs = sm + OF_HS + s * 64;
            float* rs = sm + OF_RS + s * 64;
            float t1 = __ldg(cb1 + lane), t2 = __ldg(cb1 + o2);
            #pragma unroll
            for (int k = 0; k < 16; k++) {
                float cv = __ldg(covs + b*16 + k);
                t1 = fmaf(cv, __ldg(cW1 + lane*16 + k), t1);
                t2 = fmaf(cv, __ldg(cW1 + o2*16   + k), t2);
            }
            rs[lane] = fmaxf(t1, 0.f); rs[o2] = fmaxf(t2, 0.f);
            __syncwarp();
            float a1 = __ldg(cb2 + lane), a2 = __ldg(cb2 + o2);
            #pragma unroll 8
            for (int c = 0; c < 64; c++) {
                float tv = rs[c];
                a1 = fmaf(tv, __ldg(cW2 + lane*64 + c), a1);
                a2 = fmaf(tv, __ldg(cW2 + o2*64   + c), a2);
            }
            __syncwarp();
            hs[lane] = tanh_f(a1); hs[o2] = tanh_f(a2);
            __syncwarp();
        }
    }
    // t=0 prefetch stores (buffer 0)
    if (tid >= 96 && tid < 104) {
        const int s = tid - 96;
        swin[s] = pw0;
        if (pw0 >= 0) {
            const float4* xp = (const float4*)(X + (size_t)pw0 * 8);
            float4 xa = __ldg(xp), xb = __ldg(xp + 1);
            float4* dst = (float4*)(sm + OF_XV + s * 8);
            dst[0] = xa; dst[1] = xb;
        }
    }
    __syncthreads();

    // ---- per-thread stationary pointers & biases ----
    const ulonglong2* pA = (const ulonglong2*)(sm +
        ((tid < 64) ? OF_GHR + j*68 : OF_W1 + j*68));
    const ulonglong2* pB = (const ulonglong2*)(sm +
        ((tid < 64) ? OF_GHZ + j*68 : OF_W1 + (j+64)*68));
    const ulonglong2* pG  = (const ulonglong2*)(sm + OF_GHH + j*68);
    const ulonglong2* pEr = (const ulonglong2*)(sm + OF_WHH + j*68);
    // pEz = pEr + 1088 ul2, pEn = pEr + 2176 ul2 (64*68 floats each)
    const float* pXr = sm + OF_WIH + j*12;
    const float* pXz = sm + OF_WIH + (64+j)*12;
    const float* pXn = sm + OF_WIH + (128+j)*12;

    const float ebr = sm[OF_BIH + j]      + sm[OF_BHH + j];
    const float ebz = sm[OF_BIH + 64 + j] + sm[OF_BHH + 64 + j];
    const float ebi = sm[OF_BIH + 128 + j];
    const float ebh = sm[OF_BHH + 128 + j];
    const float xr  = sm[OF_GXB + j];
    const float xz  = sm[OF_GXB + 64 + j];
    const float xh  = sm[OF_GXB + 128 + j];
    const float b1a = sm[OF_OB1 + j];
    const float b1b = sm[OF_OB1 + 64 + j];

    // head role (t>=64): uu=j, 4 threads per (sample, out) pair
    const int oidx = j >> 2, part = j & 3, s_h = oidx >> 1, o_h = oidx & 1;
    const float b2r = sm[OF_OB2 + o_h];
    float4 w2v[8];
    {
        const float4* wp = (const float4*)(sm + OF_W2 + o_h*128 + part*32);
        #pragma unroll
        for (int i = 0; i < 8; i++) w2v[i] = wp[i];
    }

    const ulonglong2* hp[8];
    #pragma unroll
    for (int s = 0; s < 8; s++)
        hp[s] = (const ulonglong2*)(sm + OF_HS + s*64);
    // rh[s][i] == hp[s][i + 128]   (OF_RS = OF_HS + 512 floats)

    float zreg[8], hcur[8];

    // ================= main time loop =================
    for (int t = 0; ; t++) {
        const int pb = t & 1;

        // prefetch winner for t+1 (threads 96..103)
        int pw = -1;
        const bool pf = (t + 1 < NEV) && (tid >= 96) && (tid < 104);
        if (pf) pw = __ldg(g_winner + (t+1)*B_ + blk*8 + (tid - 96));

        // ---- events: fired samples alternate between thread halves ----
        if (t < NEV) {
            int cnt = 0, mylist = 0, mycnt = 0;
            #pragma unroll
            for (int s = 0; s < 8; s++) {
                int w = swin[pb*8 + s];
                if (w >= 0) {
                    if ((cnt & 1) == grp) { mylist |= s << (4*mycnt); mycnt++; }
                    cnt++;
                }
            }
            if (cnt > 0) {                      // uniform across block
                float hn[4];
                #pragma unroll
                for (int e = 0; e < 4; e++) {
                    if (e < mycnt) {
                        const int s = (mylist >> (4*e)) & 7;
                        const float* xvp = sm + OF_XV + pb*64 + s*8;
                        float4 xa = *(const float4*)xvp;
                        float4 xb = *(const float4*)(xvp + 4);
                        float gir = dot8(pXr, xa, xb);
                        float giz = dot8(pXz, xa, xb);
                        float gin = dot8(pXn, xa, xb);
                        ull ar = 0, az = 0, an = 0;
                        #pragma unroll
                        for (int i = 0; i < 16; i++) {
                            ulonglong2 hv = hp[s][i];
                            ulonglong2 wr = pEr[i];
                            ulonglong2 wz = pEr[i + 1088];
                            ulonglong2 wn = pEr[i + 2176];
                            FMA2(ar, wr.x, hv.x, ar); FMA2(ar, wr.y, hv.y, ar);
                            FMA2(az, wz.x, hv.x, az); FMA2(az, wz.y, hv.y, az);
                            FMA2(an, wn.x, hv.x, an); FMA2(an, wn.y, hv.y, an);
                        }
                        float r = sigm(gir + hadd2(ar) + ebr);
                        float z = sigm(giz + hadd2(az) + ebz);
                        float n = tanh_f(gin + ebi + r * (hadd2(an) + ebh));
                        float hold = sm[OF_HS + s*64 + j];
                        hn[e] = fmaf(z, hold - n, n);     // (1-z)n + z h
                    }
                }
                __syncthreads();                // all reads of old h done
                #pragma unroll
                for (int e = 0; e < 4; e++)
                    if (e < mycnt) {
                        const int s = (mylist >> (4*e)) & 7;
                        sm[OF_HS + s*64 + j] = hn[e];
                    }
                __syncthreads();                // new h visible
            }
        }

        // ---- PASS1: thread's 2 rows vs all 8 samples ----
        ull acA[8], acB[8];
        #pragma unroll
        for (int s = 0; s < 8; s++) { acA[s] = 0; acB[s] = 0; }
        #pragma unroll
        for (int i = 0; i < 16; i++) {
            ulonglong2 wa = pA[i], wb = pB[i];
            #pragma unroll
            for (int s = 0; s < 8; s++) {
                ulonglong2 hv = hp[s][i];
                FMA2(acA[s], wa.x, hv.x, acA[s]); FMA2(acA[s], wa.y, hv.y, acA[s]);
                FMA2(acB[s], wb.x, hv.x, acB[s]); FMA2(acB[s], wb.y, hv.y, acB[s]);
            }
        }
        if (tid < 64) {
            #pragma unroll
            for (int s = 0; s < 8; s++) {
                hcur[s] = sm[OF_HS + s*64 + j];
                float r = sigm(hadd2(acA[s]) + xr);
                zreg[s] = sigm(hadd2(acB[s]) + xz);
                sm[OF_RS + s*64 + j] = r * hcur[s];
            }
        } else {
            #pragma unroll
            for (int s = 0; s < 8; s++) {
                float d0 = fmaxf(hadd2(acA[s]) + b1a, 0.f);
                float d1 = fmaxf(hadd2(acB[s]) + b1b, 0.f);
                sm[OF_DD + s*132 + j]      = d0;
                sm[OF_DD + s*132 + 64 + j] = d1;
            }
        }
        // prefetch: store winner, issue dependent X load
        float4 pxa = {0,0,0,0}, pxb = {0,0,0,0};
        if (pf) {
            swin[(pb ^ 1)*8 + (tid - 96)] = pw;
            if (pw >= 0) {
                const float4* xp = (const float4*)(X + (size_t)pw * 8);
                pxa = __ldg(xp); pxb = __ldg(xp + 1);
            }
        }
        __syncthreads();                        // rh + dd ready

        if (tid >= 64) {
            // ---- output head: out[t][s_h][o_h], 4-way partial + shuffle ----
            float p = 0.f;
            const float4* dp = (const float4*)(sm + OF_DD + s_h*132 + part*32);
            #pragma unroll
            for (int i = 0; i < 8; i++) {
                float4 d = dp[i], w = w2v[i];
                p = fmaf(d.x, w.x, p); p = fmaf(d.y, w.y, p);
                p = fmaf(d.z, w.z, p); p = fmaf(d.w, w.w, p);
            }
            p += __shfl_xor_sync(0xffffffffu, p, 1);
            p += __shfl_xor_sync(0xffffffffu, p, 2);
            if (part == 0)
                out[(size_t)t * (B_*2) + (blk*8 + s_h)*2 + o_h] = p + b2r;
            if (pf && pw >= 0) {
                float4* dst = (float4*)(sm + OF_XV + (pb ^ 1)*64 + (tid - 96)*8);
                dst[0] = pxa; dst[1] = pxb;
            }
        }
        if (t == NSTEPS) break;

        if (tid < 64) {
            // ---- PASS2: ghh row j on (r*h), all 8 samples; Euler ----
            ull g0[8];
            #pragma unroll
            for (int s = 0; s < 8; s++) g0[s] = 0;
            #pragma unroll
            for (int i = 0; i < 16; i++) {
                ulonglong2 wg = pG[i];
                #pragma unroll
                for (int s = 0; s < 8; s++) {
                    ulonglong2 rv = hp[s][i + 128];    // rh region
                    FMA2(g0[s], wg.x, rv.x, g0[s]);
                    FMA2(g0[s], wg.y, rv.y, g0[s]);
                }
            }
            #pragma unroll
            for (int s = 0; s < 8; s++) {
                float u = tanh_f(xh + hadd2(g0[s]));
                float h = hcur[s];
                sm[OF_HS + s*64 + j] = fmaf(DT_ * (1.f - zreg[s]), u - h, h);
            }
        }
        __syncthreads();                        // h updated for next step
    }
}

extern "C" void kernel_launch(void* const* d_in, const int* in_sizes, int n_in,
                              void* d_out, int out_size)
{
    (void)in_sizes; (void)n_in; (void)out_size;
    const float* X    = (const float*)d_in[2];
    const int*   sid  = (const int*)  d_in[3];
    const float* covs = (const float*)d_in[4];
    const float* cW1  = (const float*)d_in[6];
    const float* cb1  = (const float*)d_in[7];
    const float* cW2  = (const float*)d_in[8];
    const float* cb2  = (const float*)d_in[9];
    const float* gWih = (const float*)d_in[10];
    const float* gWhh = (const float*)d_in[11];
    const float* gbih = (const float*)d_in[12];
    const float* gbhh = (const float*)d_in[13];
    const float* gxb  = (const float*)d_in[15];
    const float* ghrW = (const float*)d_in[16];
    const float* ghzW = (const float*)d_in[17];
    const float* ghhW = (const float*)d_in[18];
    const float* oW1  = (const float*)d_in[19];
    const float* ob1  = (const float*)d_in[20];
    const float* oW2  = (const float*)d_in[21];
    const float* ob2  = (const float*)d_in[22];
    float* out = (float*)d_out;

    winner_init_k<<<(NEV * B_ + 255) / 256, 256>>>();
    winner_scatter_k<<<(TOT_ + 255) / 256, 256>>>(sid);

    size_t smem = SMEM_FLOATS * sizeof(float);
    cudaFuncSetAttribute(ev_gru_main, cudaFuncAttributeMaxDynamicSharedMemorySize, (int)smem);
    ev_gru_main<<<B_ / 8, 128, smem>>>(X, covs, cW1, cb1, cW2, cb2,
                                       gWih, gWhh, gbih, gbhh, gxb,
                                       ghrW, ghzW, ghhW, oW1, ob1, oW2, ob2, out);
}